// round 12
// baseline (speedup 1.0000x reference)
#include <cuda_runtime.h>
#include <math.h>
#include <stdint.h>

#define NB   16
#define NT   1000
#define NF   512
#define NH   512
#define NSEQ 2000
#define MROWS (NB*NT)   /* 16000 */
#define DOUT  1024      /* 2H */

#define GBM 128
#define GBN 128
#define GBK 16

typedef unsigned long long ull;

// ---------------- f32x2 packed helpers (sm_100+) ----------------
__device__ __forceinline__ ull f2pk(float lo, float hi) {
    ull r; asm("mov.b64 %0, {%1, %2};" : "=l"(r) : "f"(lo), "f"(hi)); return r;
}
__device__ __forceinline__ float2 f2unpk(ull v) {
    float2 r; asm("mov.b64 {%0, %1}, %2;" : "=f"(r.x), "=f"(r.y) : "l"(v)); return r;
}
__device__ __forceinline__ void fma2(ull& d, ull a, ull b) {
    asm("fma.rn.f32x2 %0, %1, %2, %0;" : "+l"(d) : "l"(a), "l"(b));
}

// ---------------- cluster / DSMEM helpers ----------------
__device__ __forceinline__ uint32_t smem_u32(const void* p) {
    uint32_t a;
    asm("{ .reg .u64 t; cvta.to.shared.u64 t, %1; cvt.u32.u64 %0, t; }" : "=r"(a) : "l"(p));
    return a;
}
__device__ __forceinline__ uint32_t mapa_u32(uint32_t addr, uint32_t rank) {
    uint32_t r;
    asm("mapa.shared::cluster.u32 %0, %1, %2;" : "=r"(r) : "r"(addr), "r"(rank));
    return r;
}
__device__ __forceinline__ void st_cluster_v4(uint32_t addr, float4 v) {
    asm volatile("st.shared::cluster.v4.f32 [%0], {%1, %2, %3, %4};"
                 :: "r"(addr), "f"(v.x), "f"(v.y), "f"(v.z), "f"(v.w) : "memory");
}
__device__ __forceinline__ void mbar_init(uint32_t a, uint32_t cnt) {
    asm volatile("mbarrier.init.shared.b64 [%0], %1;" :: "r"(a), "r"(cnt) : "memory");
}
__device__ __forceinline__ void mbar_arrive_cluster(uint32_t a) {
    asm volatile("mbarrier.arrive.release.cluster.shared::cluster.b64 _, [%0];"
                 :: "r"(a) : "memory");
}
__device__ __forceinline__ void mbar_wait(uint32_t a, uint32_t parity) {
    uint32_t done;
    do {
        asm volatile("{\n\t.reg .pred p;\n\t"
                     "mbarrier.try_wait.parity.acquire.cluster.shared::cta.b64 p, [%1], %2;\n\t"
                     "selp.b32 %0, 1, 0, p;\n\t}"
                     : "=r"(done) : "r"(a), "r"(parity) : "memory");
    } while (!done);
}
__device__ __forceinline__ void cluster_arrive_wait() {
    asm volatile("barrier.cluster.arrive.aligned;" ::: "memory");
    asm volatile("barrier.cluster.wait.aligned;" ::: "memory");
}
__device__ __forceinline__ uint32_t ctarank() {
    uint32_t r; asm("mov.u32 %0, %%cluster_ctarank;" : "=r"(r)); return r;
}

// ---------------- scratch (device globals; no runtime allocation) ----------------
__device__ float g_Wpre[MROWS*DOUT];        // [b][t][n]  BN(x@[Wz;Wh]^T+b)
__device__ float g_H[NSEQ*NB*NH];           // [s][b][j]  all hidden states
__device__ float g_ln[MROWS*DOUT];          // layernorm output
__device__ float g_hbuf[8][2][2*NH];        // fallback path only
__device__ int   g_arrv[8];                 // fallback path only
__device__ float g_scale[DOUT];             // folded BN scale
__device__ float g_shift[DOUT];             // folded BN shift (incl. gemm bias)

// ---------------- setup: fold BN + bias, reset counters ----------------
__global__ void setup_kernel(const float* __restrict__ bz, const float* __restrict__ bh,
                             const float* __restrict__ zg, const float* __restrict__ zb,
                             const float* __restrict__ zm, const float* __restrict__ zv,
                             const float* __restrict__ hg, const float* __restrict__ hb,
                             const float* __restrict__ hm, const float* __restrict__ hv)
{
    int n = blockIdx.x * blockDim.x + threadIdx.x;
    if (n < 512) {
        float sc = zg[n] * rsqrtf(zv[n] + 1e-5f);
        g_scale[n] = sc;
        g_shift[n] = (bz[n] - zm[n]) * sc + zb[n];
    } else if (n < 1024) {
        int m = n - 512;
        float sc = hg[m] * rsqrtf(hv[m] + 1e-5f);
        g_scale[n] = sc;
        g_shift[n] = (bh[m] - hm[m]) * sc + hb[m];
    }
    if (blockIdx.x == 0 && threadIdx.x < 8) g_arrv[threadIdx.x] = 0;
}

__global__ void dummy_kernel() {}   // ncu capture-slot alignment

// ---------------- 128x128x16 f32x2 GEMM, pack-free inner loop ----------------
template<int MODE>
__global__ __launch_bounds__(256, 2)
void gemm_nt2(const float* __restrict__ A,
              const float* __restrict__ B0, const float* __restrict__ B1, int nsplit,
              float* __restrict__ C, int M, int N, int K,
              const float* __restrict__ e0, const float* __restrict__ e1)
{
    __shared__ ull   As2[2][GBK][GBM + 2];
    __shared__ float Bs [2][GBK][GBN + 4];

    const int m0 = blockIdx.x * GBM;
    const int n0 = blockIdx.y * GBN;
    const int tid = threadIdx.x;

    const int lr  = tid >> 1;
    const int lks = (tid & 1) * 8;

    const int tx = tid & 15;
    const int ty = tid >> 4;

    const int nrow = n0 + lr;
    const float* brow = (nrow < nsplit) ? (B0 + (size_t)nrow * K)
                                        : (B1 + (size_t)(nrow - nsplit) * K);
    const float* arow = A + (size_t)(m0 + lr) * K;

    ull acc[2][4][2][2];
#pragma unroll
    for (int a = 0; a < 2; a++)
#pragma unroll
        for (int i = 0; i < 4; i++)
#pragma unroll
            for (int b = 0; b < 2; b++) { acc[a][i][b][0] = 0ull; acc[a][i][b][1] = 0ull; }

    const int nt = K / GBK;
    float4 ga0, ga1, gb0, gb1;

    ga0 = *(const float4*)(arow + lks);     ga1 = *(const float4*)(arow + lks + 4);
    gb0 = *(const float4*)(brow + lks);     gb1 = *(const float4*)(brow + lks + 4);
#pragma unroll
    for (int i = 0; i < 4; i++) {
        float a0 = ((const float*)&ga0)[i], a1 = ((const float*)&ga1)[i];
        As2[0][lks + i][lr]     = f2pk(a0, a0);
        As2[0][lks + 4 + i][lr] = f2pk(a1, a1);
        Bs[0][lks + i][lr]      = ((const float*)&gb0)[i];
        Bs[0][lks + 4 + i][lr]  = ((const float*)&gb1)[i];
    }
    __syncthreads();

    for (int t = 0; t < nt; t++) {
        const int cur = t & 1;
        if (t + 1 < nt) {
            const int k0 = (t + 1) * GBK;
            ga0 = *(const float4*)(arow + k0 + lks); ga1 = *(const float4*)(arow + k0 + lks + 4);
            gb0 = *(const float4*)(brow + k0 + lks); gb1 = *(const float4*)(brow + k0 + lks + 4);
        }

#pragma unroll
        for (int k = 0; k < GBK; k++) {
            const ull*   ar = &As2[cur][k][0];
            const float* br = &Bs[cur][k][0];
            ulonglong2 a01 = *(const ulonglong2*)(ar + ty * 4);
            ulonglong2 a23 = *(const ulonglong2*)(ar + ty * 4 + 2);
            ulonglong2 a45 = *(const ulonglong2*)(ar + 64 + ty * 4);
            ulonglong2 a67 = *(const ulonglong2*)(ar + 64 + ty * 4 + 2);
            ulonglong2 b01 = *(const ulonglong2*)(br + tx * 4);
            ulonglong2 b23 = *(const ulonglong2*)(br + 64 + tx * 4);

            fma2(acc[0][0][0][0], a01.x, b01.x); fma2(acc[0][0][0][1], a01.x, b01.y);
            fma2(acc[0][0][1][0], a01.x, b23.x); fma2(acc[0][0][1][1], a01.x, b23.y);
            fma2(acc[0][1][0][0], a01.y, b01.x); fma2(acc[0][1][0][1], a01.y, b01.y);
            fma2(acc[0][1][1][0], a01.y, b23.x); fma2(acc[0][1][1][1], a01.y, b23.y);
            fma2(acc[0][2][0][0], a23.x, b01.x); fma2(acc[0][2][0][1], a23.x, b01.y);
            fma2(acc[0][2][1][0], a23.x, b23.x); fma2(acc[0][2][1][1], a23.x, b23.y);
            fma2(acc[0][3][0][0], a23.y, b01.x); fma2(acc[0][3][0][1], a23.y, b01.y);
            fma2(acc[0][3][1][0], a23.y, b23.x); fma2(acc[0][3][1][1], a23.y, b23.y);
            fma2(acc[1][0][0][0], a45.x, b01.x); fma2(acc[1][0][0][1], a45.x, b01.y);
            fma2(acc[1][0][1][0], a45.x, b23.x); fma2(acc[1][0][1][1], a45.x, b23.y);
            fma2(acc[1][1][0][0], a45.y, b01.x); fma2(acc[1][1][0][1], a45.y, b01.y);
            fma2(acc[1][1][1][0], a45.y, b23.x); fma2(acc[1][1][1][1], a45.y, b23.y);
            fma2(acc[1][2][0][0], a67.x, b01.x); fma2(acc[1][2][0][1], a67.x, b01.y);
            fma2(acc[1][2][1][0], a67.x, b23.x); fma2(acc[1][2][1][1], a67.x, b23.y);
            fma2(acc[1][3][0][0], a67.y, b01.x); fma2(acc[1][3][0][1], a67.y, b01.y);
            fma2(acc[1][3][1][0], a67.y, b23.x); fma2(acc[1][3][1][1], a67.y, b23.y);
        }

        if (t + 1 < nt) {
            const int nxt = (t + 1) & 1;
#pragma unroll
            for (int i = 0; i < 4; i++) {
                float a0 = ((const float*)&ga0)[i], a1 = ((const float*)&ga1)[i];
                As2[nxt][lks + i][lr]     = f2pk(a0, a0);
                As2[nxt][lks + 4 + i][lr] = f2pk(a1, a1);
                Bs[nxt][lks + i][lr]      = ((const float*)&gb0)[i];
                Bs[nxt][lks + 4 + i][lr]  = ((const float*)&gb1)[i];
            }
            __syncthreads();
        }
    }

#pragma unroll
    for (int mb = 0; mb < 2; mb++)
#pragma unroll
        for (int i = 0; i < 4; i++) {
            const int m = m0 + mb * 64 + ty * 4 + i;
#pragma unroll
            for (int nb = 0; nb < 2; nb++) {
                const int n = n0 + nb * 64 + tx * 4;
                float2 p0 = f2unpk(acc[mb][i][nb][0]);
                float2 p1 = f2unpk(acc[mb][i][nb][1]);
                float4 v = make_float4(p0.x, p0.y, p1.x, p1.y);
                if (MODE == 0) {
                    float4 s = *(const float4*)&e0[n];
                    float4 h = *(const float4*)&e1[n];
                    v.x = v.x * s.x + h.x; v.y = v.y * s.y + h.y;
                    v.z = v.z * s.z + h.z; v.w = v.w * s.w + h.w;
                } else {
                    float4 bb = *(const float4*)&e0[n];
                    v.x = tanhf(v.x + bb.x); v.y = tanhf(v.y + bb.y);
                    v.z = tanhf(v.z + bb.z); v.w = tanhf(v.w + bb.w);
                }
                *(float4*)&C[(size_t)m * N + n] = v;
            }
        }
}

// ---------------- LiGRU recurrence: 16-CTA cluster, cooperative DSMEM push ----------------
// 8 clusters x 16 CTAs. Cluster g owns GLOBAL batch rows {2g, 2g+1}; CTA rank c owns
// j in [32c, 32c+32). Per step: compute -> leaders stage slice in LOCAL hsm[p^1] ->
// bar -> cooperative push (1 st.shared::cluster.v4 per thread: peer=tid>>4, chunk=tid&15)
// -> bar -> 16 parallel arrive threads -> local mbarrier parity wait. Two alternating
// mbarriers prevent phase mixing; <=1-step skew makes double-buffered hsm safe.
__global__ __launch_bounds__(256, 1)
void ligru_cluster_kernel(const float* __restrict__ U)
{
    const int g   = blockIdx.x >> 4;
    const int c   = ctarank();                   // == blockIdx.x & 15
    const int tid = threadIdx.x;
    const int l   = tid & 31;
    const int jl  = (tid >> 5) * 4 + (l >> 3);   // 0..31
    const int j   = c * 32 + jl;                 // 0..511
    const int gate= (l >> 2) & 1;
    const int ks  = l & 3;

    // U slice in registers: 128 floats (one gate, one j, interleaved k-granules)
    ull U2[64];
    {
        const ulonglong2* up = (const ulonglong2*)(U + (size_t)(gate * 512 + j) * NH) + ks;
#pragma unroll
        for (int q = 0; q < 32; q++) {
            ulonglong2 t = up[q * 4];
            U2[2*q] = t.x; U2[2*q+1] = t.y;
        }
    }

    __shared__ float hsm[2][2 * NH];    // [parity][b*512 + j], 8 KB
    __shared__ float Wbuf[2][128];      // [parity][b*64 + gate*32 + jl]
    __shared__ __align__(8) ull mbar[2];

    for (int i = tid; i < 4 * NH; i += 256) ((float*)hsm)[i] = 0.f;
    if (tid == 0) { mbar_init(smem_u32(&mbar[0]), 16); mbar_init(smem_u32(&mbar[1]), 16); }

    // per-thread peer addresses
    const uint32_t hloc = smem_u32(hsm);
    const uint32_t mloc = smem_u32(mbar);
    const int pr = tid >> 4;                       // push peer (0..15)
    const int q  = tid & 15;                       // push chunk (0..15)
    const uint32_t pushB = mapa_u32(hloc, pr);     // peer hsm base
    const uint32_t arrB  = (tid < 16) ? mapa_u32(mloc, tid) : 0;  // peer mbar base
    const uint32_t chunk_off = (uint32_t)((q >> 3) * 2048 + c * 128 + (q & 7) * 16);

    // Wpre prefetch (tid < 128): pbg = GLOBAL batch row; depth-3
    const int pb  = tid >> 6;
    const int pbg = 2 * g + pb;
    const int pg  = (tid >> 5) & 1;
    const int pj  = tid & 31;
    const float* wcol = g_Wpre + (size_t)pg * 512 + c * 32 + pj;
    float pfA = 0.f, pfB = 0.f;
    if (tid < 128) {
        Wbuf[0][tid] = __ldg(wcol + ((size_t)pbg * NT + 0) * DOUT);
        pfA          = __ldg(wcol + ((size_t)pbg * NT + 1) * DOUT);
        pfB          = __ldg(wcol + ((size_t)pbg * NT + 2) * DOUT);
    }
    __syncthreads();
    cluster_arrive_wait();   // peers' mbar init + hsm zero visible before any push

    const bool lead = ((l & 7) == 0);

#pragma unroll 1
    for (int s = 0; s < NSEQ; s++) {
        const int p = s & 1;

        // stage W for s+1; rotate; issue load for s+3
        if (tid < 128) {
            Wbuf[p ^ 1][tid] = pfA;
            pfA = pfB;
            int s3 = s + 3; if (s3 > NSEQ - 1) s3 = NSEQ - 1;
            int srcb = (s3 < NT) ? pbg : (NB - 1 - pbg);
            int tt   = (s3 < NT) ? s3  : (s3 - NT);
            pfB = __ldg(wcol + ((size_t)srcb * NT + tt) * DOUT);
        }

        // partial dots over interleaved granules, both batches (f32x2)
        ull acc0 = 0ull, acc1 = 0ull;
        {
            const ulonglong2* h0 = (const ulonglong2*)&hsm[p][0] + ks;
            const ulonglong2* h1 = (const ulonglong2*)&hsm[p][NH] + ks;
#pragma unroll
            for (int qq = 0; qq < 32; qq++) {
                ulonglong2 v0 = h0[qq * 4];
                fma2(acc0, U2[2*qq], v0.x); fma2(acc0, U2[2*qq+1], v0.y);
                ulonglong2 v1 = h1[qq * 4];
                fma2(acc1, U2[2*qq], v1.x); fma2(acc1, U2[2*qq+1], v1.y);
            }
        }
        float2 q0 = f2unpk(acc0), q1 = f2unpk(acc1);
        float a0 = q0.x + q0.y, a1 = q1.x + q1.y;
        a0 += __shfl_xor_sync(0xffffffffu, a0, 1);
        a1 += __shfl_xor_sync(0xffffffffu, a1, 1);
        a0 += __shfl_xor_sync(0xffffffffu, a0, 2);
        a1 += __shfl_xor_sync(0xffffffffu, a1, 2);
        float o0 = __shfl_xor_sync(0xffffffffu, a0, 4);
        float o1 = __shfl_xor_sync(0xffffffffu, a1, 4);

        float hn0 = 0.f, hn1 = 0.f;
        if (lead) {   // gate==0, ks==0: a=uz, o=uh
            const float* wb = Wbuf[p];
            float wz0 = wb[jl],       wh0 = wb[32 + jl];
            float wz1 = wb[64 + jl],  wh1 = wb[96 + jl];
            float zt0 = 1.f / (1.f + expf(-(wz0 + a0)));
            float hc0 = fmaxf(wh0 + o0, 0.f);
            hn0 = zt0 * hsm[p][j] + (1.f - zt0) * hc0;
            float zt1 = 1.f / (1.f + expf(-(wz1 + a1)));
            float hc1 = fmaxf(wh1 + o1, 0.f);
            hn1 = zt1 * hsm[p][NH + j] + (1.f - zt1) * hc1;

            hsm[p ^ 1][j]      = hn0;     // stage own slice locally
            hsm[p ^ 1][NH + j] = hn1;
        }
        __syncthreads();                  // staged slice complete

        // cooperative push: one st.shared::cluster.v4 per thread
        {
            const uint32_t boff = (uint32_t)((p ^ 1) * 4096) + chunk_off;
            float4 v = *(const float4*)((const char*)hsm + boff);
            st_cluster_v4(pushB + boff, v);
        }
        __syncthreads();                  // all pushes issued & CTA-ordered

        if (tid < 16) mbar_arrive_cluster(arrB + (uint32_t)p * 8);
        mbar_wait(mloc + (uint32_t)p * 8, (s >> 1) & 1);

        // g_H archive (off the exchange-critical path)
        if (lead) {
            __stcg(g_H + ((size_t)s * NB + 2 * g)     * NH + j, hn0);
            __stcg(g_H + ((size_t)s * NB + 2 * g + 1) * NH + j, hn1);
        }
    }

    cluster_arrive_wait();   // no CTA exits while peers may still push into its smem
}

// ---------------- fallback: global-sync recurrence (if cluster launch rejected) ----------------
__global__ __launch_bounds__(256, 1)
void ligru_global_kernel(const float* __restrict__ U)
{
    const int g   = blockIdx.x >> 4;
    const int c   = blockIdx.x & 15;
    const int tid = threadIdx.x;
    const int l   = tid & 31;
    const int jl  = (tid >> 5) * 4 + (l >> 3);
    const int j   = c * 32 + jl;
    const int gate= (l >> 2) & 1;
    const int ks  = l & 3;

    ull U2[64];
    {
        const ulonglong2* up = (const ulonglong2*)(U + (size_t)(gate * 512 + j) * NH) + ks;
#pragma unroll
        for (int q = 0; q < 32; q++) {
            ulonglong2 t = up[q * 4];
            U2[2*q] = t.x; U2[2*q+1] = t.y;
        }
    }

    __shared__ float hsm[2 * NH];
    __shared__ float Wbuf[2][128];
    for (int i = tid; i < 2 * NH; i += 256) hsm[i] = 0.f;

    const int pb  = tid >> 6;
    const int pbg = 2 * g + pb;
    const int pg  = (tid >> 5) & 1;
    const int pj  = tid & 31;
    const float* wcol = g_Wpre + (size_t)pg * 512 + c * 32 + pj;
    float pfA = 0.f, pfB = 0.f;
    if (tid < 128) {
        Wbuf[0][tid] = __ldg(wcol + ((size_t)pbg * NT + 0) * DOUT);
        pfA          = __ldg(wcol + ((size_t)pbg * NT + 1) * DOUT);
        pfB          = __ldg(wcol + ((size_t)pbg * NT + 2) * DOUT);
    }
    __syncthreads();

    const bool lead = ((l & 7) == 0);

#pragma unroll 1
    for (int s = 0; s < NSEQ; s++) {
        if (tid < 128) {
            Wbuf[(s + 1) & 1][tid] = pfA;
            pfA = pfB;
            int s3 = s + 3; if (s3 > NSEQ - 1) s3 = NSEQ - 1;
            int srcb = (s3 < NT) ? pbg : (NB - 1 - pbg);
            int tt   = (s3 < NT) ? s3  : (s3 - NT);
            pfB = __ldg(wcol + ((size_t)srcb * NT + tt) * DOUT);
        }

        ull acc0 = 0ull, acc1 = 0ull;
        {
            const ulonglong2* h0 = (const ulonglong2*)&hsm[0] + ks;
            const ulonglong2* h1 = (const ulonglong2*)&hsm[NH] + ks;
#pragma unroll
            for (int q = 0; q < 32; q++) {
                ulonglong2 v0 = h0[q * 4];
                fma2(acc0, U2[2*q], v0.x); fma2(acc0, U2[2*q+1], v0.y);
                ulonglong2 v1 = h1[q * 4];
                fma2(acc1, U2[2*q], v1.x); fma2(acc1, U2[2*q+1], v1.y);
            }
        }
        float2 q0 = f2unpk(acc0), q1 = f2unpk(acc1);
        float a0 = q0.x + q0.y, a1 = q1.x + q1.y;
        a0 += __shfl_xor_sync(0xffffffffu, a0, 1);
        a1 += __shfl_xor_sync(0xffffffffu, a1, 1);
        a0 += __shfl_xor_sync(0xffffffffu, a0, 2);
        a1 += __shfl_xor_sync(0xffffffffu, a1, 2);
        float o0 = __shfl_xor_sync(0xffffffffu, a0, 4);
        float o1 = __shfl_xor_sync(0xffffffffu, a1, 4);

        float hn0 = 0.f, hn1 = 0.f;
        if (lead) {
            const float* wb = Wbuf[s & 1];
            float wz0 = wb[jl],       wh0 = wb[32 + jl];
            float wz1 = wb[64 + jl],  wh1 = wb[96 + jl];
            float zt0 = 1.f / (1.f + expf(-(wz0 + a0)));
            float hc0 = fmaxf(wh0 + o0, 0.f);
            hn0 = zt0 * hsm[j] + (1.f - zt0) * hc0;
            float zt1 = 1.f / (1.f + expf(-(wz1 + a1)));
            float hc1 = fmaxf(wh1 + o1, 0.f);
            hn1 = zt1 * hsm[NH + j] + (1.f - zt1) * hc1;

            float* hb = &g_hbuf[g][s & 1][0];
            __stcg(hb + j,      hn0);
            __stcg(hb + NH + j, hn1);
            __threadfence();
        }
        __syncthreads();

        if (tid == 0) {
            atomicAdd(&g_arrv[g], 1);
            const int target = 16 * (s + 1);
            volatile int* a = (volatile int*)&g_arrv[g];
            while (*a < target) { }
        }
        __syncthreads();

        if (lead) {
            __stcg(g_H + ((size_t)s * NB + 2 * g)     * NH + j, hn0);
            __stcg(g_H + ((size_t)s * NB + 2 * g + 1) * NH + j, hn1);
        }
        {
            const float4* src = (const float4*)&g_hbuf[g][s & 1][0];
            float4 hv = __ldcg(src + tid);
            *(float4*)&hsm[tid * 4] = hv;
        }
        __syncthreads();
    }
}

// ---------------- LayerNorm over gathered bidirectional output ----------------
__global__ __launch_bounds__(256)
void ln_kernel(const float* __restrict__ lng, const float* __restrict__ lnb)
{
    const int r = blockIdx.x;
    const int b = r / NT, t = r - b * NT;
    const int tid = threadIdx.x;

    const float* s0 = g_H + ((size_t)t * NB + b) * NH;
    const float* s1 = g_H + ((size_t)(NT + t) * NB + (NB - 1 - b)) * NH;

    float v0 = s0[tid], v1 = s0[tid + 256];
    float v2 = s1[tid], v3 = s1[tid + 256];

    float s  = v0 + v1 + v2 + v3;
    float sq = v0*v0 + v1*v1 + v2*v2 + v3*v3;

    for (int o = 16; o; o >>= 1) {
        s  += __shfl_down_sync(0xffffffffu, s,  o);
        sq += __shfl_down_sync(0xffffffffu, sq, o);
    }
    __shared__ float rs_[8], rq_[8];
    __shared__ float mu_s, rstd_s;
    if ((tid & 31) == 0) { rs_[tid >> 5] = s; rq_[tid >> 5] = sq; }
    __syncthreads();
    if (tid == 0) {
        float S = 0.f, Q = 0.f;
#pragma unroll
        for (int i = 0; i < 8; i++) { S += rs_[i]; Q += rq_[i]; }
        float mu = S * (1.f / 1024.f);
        float var = Q * (1.f / 1024.f) - mu * mu;
        mu_s = mu;
        rstd_s = rsqrtf(var + 1e-5f);
    }
    __syncthreads();
    const float mu = mu_s, rs = rstd_s;

    float* o = g_ln + (size_t)r * DOUT;
    o[tid]        = (v0 - mu) * rs * lng[tid]        + lnb[tid];
    o[tid + 256]  = (v1 - mu) * rs * lng[tid + 256]  + lnb[tid + 256];
    o[tid + 512]  = (v2 - mu) * rs * lng[tid + 512]  + lnb[tid + 512];
    o[tid + 768]  = (v3 - mu) * rs * lng[tid + 768]  + lnb[tid + 768];
}

// ---------------- x_len passthrough tail ----------------
__global__ void tail_kernel(const int* __restrict__ xl, float* __restrict__ out, int n)
{
    int i = threadIdx.x;
    if (i < n) out[(size_t)MROWS * DOUT + i] = (float)xl[i];
}

// ---------------- launch ----------------
extern "C" void kernel_launch(void* const* d_in, const int* in_sizes, int n_in,
                              void* d_out, int out_size)
{
    const float* x    = (const float*)d_in[0];
    const int*   xlen = (const int*)  d_in[1];
    const float* Wz   = (const float*)d_in[2];
    const float* bz   = (const float*)d_in[3];
    const float* Wh   = (const float*)d_in[4];
    const float* bh   = (const float*)d_in[5];
    const float* U    = (const float*)d_in[6];
    const float* zg   = (const float*)d_in[7];
    const float* zb   = (const float*)d_in[8];
    const float* zm   = (const float*)d_in[9];
    const float* zv   = (const float*)d_in[10];
    const float* hg   = (const float*)d_in[11];
    const float* hbb  = (const float*)d_in[12];
    const float* hm   = (const float*)d_in[13];
    const float* hv   = (const float*)d_in[14];
    const float* lng  = (const float*)d_in[15];
    const float* lnb  = (const float*)d_in[16];
    const float* pjW  = (const float*)d_in[17];
    const float* pjb  = (const float*)d_in[18];
    float* out = (float*)d_out;

    float *Wpre, *lnp, *scl, *shf;
    cudaGetSymbolAddress((void**)&Wpre, g_Wpre);
    cudaGetSymbolAddress((void**)&lnp,  g_ln);
    cudaGetSymbolAddress((void**)&scl,  g_scale);
    cudaGetSymbolAddress((void**)&shf,  g_shift);

    setup_kernel<<<4, 256>>>(bz, bh, zg, zb, zm, zv, hg, hbb, hm, hv);

    dummy_kernel<<<1, 32>>>();   // slot shift: gemm1 lands on ncu capture slot #3
    dummy_kernel<<<1, 32>>>();

    dim3 gg(MROWS / GBM, DOUT / GBN);
    gemm_nt2<0><<<gg, 256>>>(x, Wz, Wh, 512, Wpre, MROWS, DOUT, NF, scl, shf);

    // 16-CTA-cluster recurrence; fall back to global-sync variant on rejection
    {
        cudaFuncSetAttribute(ligru_cluster_kernel,
                             cudaFuncAttributeNonPortableClusterSizeAllowed, 1);
        cudaLaunchConfig_t cfg = {};
        cfg.gridDim  = dim3(128, 1, 1);
        cfg.blockDim = dim3(256, 1, 1);
        cfg.dynamicSmemBytes = 0;
        cfg.stream = 0;
        cudaLaunchAttribute at[1];
        at[0].id = cudaLaunchAttributeClusterDimension;
        at[0].val.clusterDim.x = 16;
        at[0].val.clusterDim.y = 1;
        at[0].val.clusterDim.z = 1;
        cfg.attrs = at;
        cfg.numAttrs = 1;
        cudaError_t e = cudaLaunchKernelEx(&cfg, ligru_cluster_kernel, U);
        if (e != cudaSuccess) {
            cudaGetLastError();
            ligru_global_kernel<<<128, 256>>>(U);
        }
    }

    ln_kernel<<<MROWS, 256>>>(lng, lnb);

    gemm_nt2<1><<<gg, 256>>>(lnp, pjW, pjW, DOUT, out, MROWS, DOUT, DOUT, pjb, pjb);

    int tail = out_size - MROWS * DOUT;
    if (tail > 0) tail_kernel<<<1, 32>>>(xlen, out, tail > NB ? NB : tail);
}

// round 13
// speedup vs baseline: 1.5190x; 1.5190x over previous
#include <cuda_runtime.h>
#include <math.h>
#include <stdint.h>

#define NB   16
#define NT   1000
#define NF   512
#define NH   512
#define NSEQ 2000
#define MROWS (NB*NT)   /* 16000 */
#define DOUT  1024      /* 2H */

#define GBM 128
#define GBN 128
#define GBK 16

typedef unsigned long long ull;

// ---------------- f32x2 packed helpers (sm_100+) ----------------
__device__ __forceinline__ ull f2pk(float lo, float hi) {
    ull r; asm("mov.b64 %0, {%1, %2};" : "=l"(r) : "f"(lo), "f"(hi)); return r;
}
__device__ __forceinline__ float2 f2unpk(ull v) {
    float2 r; asm("mov.b64 {%0, %1}, %2;" : "=f"(r.x), "=f"(r.y) : "l"(v)); return r;
}
__device__ __forceinline__ void fma2(ull& d, ull a, ull b) {
    asm("fma.rn.f32x2 %0, %1, %2, %0;" : "+l"(d) : "l"(a), "l"(b));
}

// ---------------- scratch (device globals; no runtime allocation) ----------------
__device__ float g_Wpre[MROWS*DOUT];        // [b][t][n]  BN(x@[Wz;Wh]^T+b)
__device__ float g_H[NSEQ*NB*NH];           // [s][b][j]  all hidden states
__device__ float g_ln[MROWS*DOUT];          // layernorm output
__device__ float g_hbuf[8][2][2*NH];        // [group][parity][b*512+j]
__device__ int   g_arrv[8];                 // per-group arrival counters
__device__ float g_scale[DOUT];             // folded BN scale
__device__ float g_shift[DOUT];             // folded BN shift (incl. gemm bias)

// ---------------- setup: fold BN + bias, reset counters ----------------
__global__ void setup_kernel(const float* __restrict__ bz, const float* __restrict__ bh,
                             const float* __restrict__ zg, const float* __restrict__ zb,
                             const float* __restrict__ zm, const float* __restrict__ zv,
                             const float* __restrict__ hg, const float* __restrict__ hb,
                             const float* __restrict__ hm, const float* __restrict__ hv)
{
    int n = blockIdx.x * blockDim.x + threadIdx.x;
    if (n < 512) {
        float sc = zg[n] * rsqrtf(zv[n] + 1e-5f);
        g_scale[n] = sc;
        g_shift[n] = (bz[n] - zm[n]) * sc + zb[n];
    } else if (n < 1024) {
        int m = n - 512;
        float sc = hg[m] * rsqrtf(hv[m] + 1e-5f);
        g_scale[n] = sc;
        g_shift[n] = (bh[m] - hm[m]) * sc + hb[m];
    }
    if (blockIdx.x == 0 && threadIdx.x < 8) g_arrv[threadIdx.x] = 0;
}

__global__ void dummy_kernel() {}   // ncu capture-slot alignment (slot lands on ligru)

// ---------------- 128x128x16 f32x2 GEMM, crossbar-balanced ----------------
// As plain floats (2x LDS.128/thread/k), Bs pairs via aligned reinterpret,
// A duplicated into (a,a) ulls in registers (8 packs on alu pipe).
// MODE 0: val = acc*e0[n] + e1[n];  MODE 1: val = tanhf(acc + e0[n])
template<int MODE>
__global__ __launch_bounds__(256, 2)
void gemm_nt2(const float* __restrict__ A,
              const float* __restrict__ B0, const float* __restrict__ B1, int nsplit,
              float* __restrict__ C, int M, int N, int K,
              const float* __restrict__ e0, const float* __restrict__ e1)
{
    __shared__ float As[2][GBK][GBM + 4];   // 132-float rows = 528B (16B-aligned)
    __shared__ float Bs[2][GBK][GBN + 4];

    const int m0 = blockIdx.x * GBM;
    const int n0 = blockIdx.y * GBN;
    const int tid = threadIdx.x;

    const int lr  = tid >> 1;          // 0..127 row
    const int lks = (tid & 1) * 8;     // k-chunk 0 or 8

    const int tx = tid & 15;           // n micro
    const int ty = tid >> 4;           // m micro

    const int nrow = n0 + lr;
    const float* brow = (nrow < nsplit) ? (B0 + (size_t)nrow * K)
                                        : (B1 + (size_t)(nrow - nsplit) * K);
    const float* arow = A + (size_t)(m0 + lr) * K;

    ull acc[2][4][2][2];
#pragma unroll
    for (int a = 0; a < 2; a++)
#pragma unroll
        for (int i = 0; i < 4; i++)
#pragma unroll
            for (int b = 0; b < 2; b++) { acc[a][i][b][0] = 0ull; acc[a][i][b][1] = 0ull; }

    const int nt = K / GBK;
    float4 ga0, ga1, gb0, gb1;

    // preload tile 0
    ga0 = *(const float4*)(arow + lks);     ga1 = *(const float4*)(arow + lks + 4);
    gb0 = *(const float4*)(brow + lks);     gb1 = *(const float4*)(brow + lks + 4);
#pragma unroll
    for (int i = 0; i < 4; i++) {
        As[0][lks + i][lr]     = ((const float*)&ga0)[i];
        As[0][lks + 4 + i][lr] = ((const float*)&ga1)[i];
        Bs[0][lks + i][lr]     = ((const float*)&gb0)[i];
        Bs[0][lks + 4 + i][lr] = ((const float*)&gb1)[i];
    }
    __syncthreads();

    for (int t = 0; t < nt; t++) {
        const int cur = t & 1;
        if (t + 1 < nt) {
            const int k0 = (t + 1) * GBK;
            ga0 = *(const float4*)(arow + k0 + lks); ga1 = *(const float4*)(arow + k0 + lks + 4);
            gb0 = *(const float4*)(brow + k0 + lks); gb1 = *(const float4*)(brow + k0 + lks + 4);
        }

#pragma unroll
        for (int k = 0; k < GBK; k++) {
            const float* arp = &As[cur][k][0];
            const float* brp = &Bs[cur][k][0];
            float4 a0 = *(const float4*)(arp + ty * 4);
            float4 a1 = *(const float4*)(arp + 64 + ty * 4);
            ulonglong2 b01 = *(const ulonglong2*)(brp + tx * 4);        // 4 floats as 2 pairs
            ulonglong2 b23 = *(const ulonglong2*)(brp + 64 + tx * 4);

            ull ap[2][4];
            ap[0][0] = f2pk(a0.x, a0.x); ap[0][1] = f2pk(a0.y, a0.y);
            ap[0][2] = f2pk(a0.z, a0.z); ap[0][3] = f2pk(a0.w, a0.w);
            ap[1][0] = f2pk(a1.x, a1.x); ap[1][1] = f2pk(a1.y, a1.y);
            ap[1][2] = f2pk(a1.z, a1.z); ap[1][3] = f2pk(a1.w, a1.w);

#pragma unroll
            for (int mb = 0; mb < 2; mb++)
#pragma unroll
                for (int i = 0; i < 4; i++) {
                    fma2(acc[mb][i][0][0], ap[mb][i], b01.x);
                    fma2(acc[mb][i][0][1], ap[mb][i], b01.y);
                    fma2(acc[mb][i][1][0], ap[mb][i], b23.x);
                    fma2(acc[mb][i][1][1], ap[mb][i], b23.y);
                }
        }

        if (t + 1 < nt) {
            const int nxt = (t + 1) & 1;
#pragma unroll
            for (int i = 0; i < 4; i++) {
                As[nxt][lks + i][lr]     = ((const float*)&ga0)[i];
                As[nxt][lks + 4 + i][lr] = ((const float*)&ga1)[i];
                Bs[nxt][lks + i][lr]     = ((const float*)&gb0)[i];
                Bs[nxt][lks + 4 + i][lr] = ((const float*)&gb1)[i];
            }
            __syncthreads();
        }
    }

#pragma unroll
    for (int mb = 0; mb < 2; mb++)
#pragma unroll
        for (int i = 0; i < 4; i++) {
            const int m = m0 + mb * 64 + ty * 4 + i;
#pragma unroll
            for (int nb = 0; nb < 2; nb++) {
                const int n = n0 + nb * 64 + tx * 4;
                float2 p0 = f2unpk(acc[mb][i][nb][0]);
                float2 p1 = f2unpk(acc[mb][i][nb][1]);
                float4 v = make_float4(p0.x, p0.y, p1.x, p1.y);
                if (MODE == 0) {
                    float4 s = *(const float4*)&e0[n];
                    float4 h = *(const float4*)&e1[n];
                    v.x = v.x * s.x + h.x; v.y = v.y * s.y + h.y;
                    v.z = v.z * s.z + h.z; v.w = v.w * s.w + h.w;
                } else {
                    float4 bb = *(const float4*)&e0[n];
                    v.x = tanhf(v.x + bb.x); v.y = tanhf(v.y + bb.y);
                    v.z = tanhf(v.z + bb.z); v.w = tanhf(v.w + bb.w);
                }
                *(float4*)&C[(size_t)m * N + n] = v;
            }
        }
}

// ---------------- persistent LiGRU recurrence (R3-verbatim, best measured) ----------------
// 128 CTAs: 8 groups x 16 CTAs. Group g owns batch rows {2g, 2g+1}.
// CTA c owns j in [32c, 32c+32). warp = k-slice (8 x 64), lane = j.
// U slice in registers as f32x2 pairs; smem-reduce across 8 warps; tid<64 epilogue;
// sync = leader stcg + threadfence; bar; tid0 atomicAdd + volatile spin; bar; ldcg reload.
__global__ __launch_bounds__(256, 1)
void ligru_kernel(const float* __restrict__ U)
{
    const int g   = blockIdx.x >> 4;   // 0..7
    const int c   = blockIdx.x & 15;   // 0..15
    const int tid = threadIdx.x;
    const int w   = tid >> 5;          // 0..7  (k-slice)
    const int l   = tid & 31;          // 0..31 (j within slice)
    const int j   = c * 32 + l;        // 0..511
    const int kb  = w * 64;            // k base

    // U slice in registers, pre-packed as f32x2 pairs (64 floats -> 32 ull per gate)
    ull Uz2[32], Uh2[32];
    {
        const ulonglong2* uz = (const ulonglong2*)(U + (size_t)j * NH + kb);
        const ulonglong2* uh = (const ulonglong2*)(U + (size_t)(512 + j) * NH + kb);
#pragma unroll
        for (int i = 0; i < 16; i++) {
            ulonglong2 a = uz[i]; Uz2[2*i] = a.x; Uz2[2*i+1] = a.y;
            ulonglong2 b = uh[i]; Uh2[2*i] = b.x; Uh2[2*i+1] = b.y;
        }
    }

    __shared__ float hsm[2 * NH];
    __shared__ float red[8][32][5];   // [warp][j][{az0,az1,ah0,ah1}] pad->5
    for (int i = tid; i < 2 * NH; i += 256) hsm[i] = 0.f;
    __syncthreads();

    const int bo = (tid >> 5) & 1;
    const int jo = tid & 31;
    const int jg = c * 32 + jo;
    const int bglob = 2 * g + bo;

#pragma unroll 1
    for (int s = 0; s < NSEQ; s++) {
        // prefetch this step's gate pre-activations
        float wzv = 0.f, whv = 0.f;
        if (tid < 64) {
            int srcb, tt;
            if (s < NT) { srcb = bglob;          tt = s; }
            else        { srcb = NB - 1 - bglob; tt = s - NT; }
            const float* wp = g_Wpre + ((size_t)srcb * NT + tt) * DOUT;
            wzv = __ldg(wp + jg);
            whv = __ldg(wp + 512 + jg);
        }

        // partial dots over this warp's k-slice, both batches, both gates (f32x2)
        ull az0 = 0ull, az1 = 0ull, ah0 = 0ull, ah1 = 0ull;
        {
            const ulonglong2* h0 = (const ulonglong2*)&hsm[0] + (kb >> 2);
            const ulonglong2* h1 = (const ulonglong2*)&hsm[NH] + (kb >> 2);
#pragma unroll
            for (int q = 0; q < 16; q++) {
                ulonglong2 v0 = h0[q];
                fma2(az0, Uz2[2*q], v0.x); fma2(az0, Uz2[2*q+1], v0.y);
                fma2(ah0, Uh2[2*q], v0.x); fma2(ah0, Uh2[2*q+1], v0.y);
                ulonglong2 v1 = h1[q];
                fma2(az1, Uz2[2*q], v1.x); fma2(az1, Uz2[2*q+1], v1.y);
                fma2(ah1, Uh2[2*q], v1.x); fma2(ah1, Uh2[2*q+1], v1.y);
            }
        }
        {
            float2 p;
            p = f2unpk(az0); red[w][l][0] = p.x + p.y;
            p = f2unpk(az1); red[w][l][1] = p.x + p.y;
            p = f2unpk(ah0); red[w][l][2] = p.x + p.y;
            p = f2unpk(ah1); red[w][l][3] = p.x + p.y;
        }
        __syncthreads();

        if (tid < 64) {
            float uz = 0.f, uh = 0.f;
#pragma unroll
            for (int ww = 0; ww < 8; ww++) {
                uz += red[ww][jo][bo];
                uh += red[ww][jo][2 + bo];
            }
            float zt = 1.f / (1.f + expf(-(wzv + uz)));
            float hc = fmaxf(whv + uh, 0.f);
            float ho = hsm[bo * NH + jg];
            float hn = zt * ho + (1.f - zt) * hc;
            g_hbuf[g][(s + 1) & 1][bo * NH + jg] = hn;
            g_H[((size_t)s * NB + bglob) * NH + jg] = hn;
            __threadfence();
        }
        __syncthreads();

        // group barrier: 16 arrivals per step (monotonic counter)
        if (tid == 0) {
            atomicAdd(&g_arrv[g], 1);
            const int target = 16 * (s + 1);
            volatile int* a = (volatile int*)&g_arrv[g];
            while (*a < target) { }
        }
        __syncthreads();

        // reload full h for the group (bypass L1)
        {
            const float* hbp = &g_hbuf[g][(s + 1) & 1][0];
            for (int i = tid; i < 2 * NH; i += 256)
                hsm[i] = __ldcg(hbp + i);
        }
        __syncthreads();
    }
}

// ---------------- LayerNorm over gathered bidirectional output ----------------
__global__ __launch_bounds__(256)
void ln_kernel(const float* __restrict__ lng, const float* __restrict__ lnb)
{
    const int r = blockIdx.x;            // 0..15999 = b*1000 + t
    const int b = r / NT, t = r - b * NT;
    const int tid = threadIdx.x;

    const float* s0 = g_H + ((size_t)t * NB + b) * NH;                   // forward
    const float* s1 = g_H + ((size_t)(NT + t) * NB + (NB - 1 - b)) * NH; // backward

    float v0 = s0[tid], v1 = s0[tid + 256];
    float v2 = s1[tid], v3 = s1[tid + 256];

    float s  = v0 + v1 + v2 + v3;
    float sq = v0*v0 + v1*v1 + v2*v2 + v3*v3;

    for (int o = 16; o; o >>= 1) {
        s  += __shfl_down_sync(0xffffffffu, s,  o);
        sq += __shfl_down_sync(0xffffffffu, sq, o);
    }
    __shared__ float rs_[8], rq_[8];
    __shared__ float mu_s, rstd_s;
    if ((tid & 31) == 0) { rs_[tid >> 5] = s; rq_[tid >> 5] = sq; }
    __syncthreads();
    if (tid == 0) {
        float S = 0.f, Q = 0.f;
#pragma unroll
        for (int i = 0; i < 8; i++) { S += rs_[i]; Q += rq_[i]; }
        float mu = S * (1.f / 1024.f);
        float var = Q * (1.f / 1024.f) - mu * mu;
        mu_s = mu;
        rstd_s = rsqrtf(var + 1e-5f);
    }
    __syncthreads();
    const float mu = mu_s, rs = rstd_s;

    float* o = g_ln + (size_t)r * DOUT;
    o[tid]        = (v0 - mu) * rs * lng[tid]        + lnb[tid];
    o[tid + 256]  = (v1 - mu) * rs * lng[tid + 256]  + lnb[tid + 256];
    o[tid + 512]  = (v2 - mu) * rs * lng[tid + 512]  + lnb[tid + 512];
    o[tid + 768]  = (v3 - mu) * rs * lng[tid + 768]  + lnb[tid + 768];
}

// ---------------- x_len passthrough tail ----------------
__global__ void tail_kernel(const int* __restrict__ xl, float* __restrict__ out, int n)
{
    int i = threadIdx.x;
    if (i < n) out[(size_t)MROWS * DOUT + i] = (float)xl[i];
}

// ---------------- launch ----------------
extern "C" void kernel_launch(void* const* d_in, const int* in_sizes, int n_in,
                              void* d_out, int out_size)
{
    const float* x    = (const float*)d_in[0];
    const int*   xlen = (const int*)  d_in[1];
    const float* Wz   = (const float*)d_in[2];
    const float* bz   = (const float*)d_in[3];
    const float* Wh   = (const float*)d_in[4];
    const float* bh   = (const float*)d_in[5];
    const float* U    = (const float*)d_in[6];
    const float* zg   = (const float*)d_in[7];
    const float* zb   = (const float*)d_in[8];
    const float* zm   = (const float*)d_in[9];
    const float* zv   = (const float*)d_in[10];
    const float* hg   = (const float*)d_in[11];
    const float* hbb  = (const float*)d_in[12];
    const float* hm   = (const float*)d_in[13];
    const float* hv   = (const float*)d_in[14];
    const float* lng  = (const float*)d_in[15];
    const float* lnb  = (const float*)d_in[16];
    const float* pjW  = (const float*)d_in[17];
    const float* pjb  = (const float*)d_in[18];
    float* out = (float*)d_out;

    float *Wpre, *lnp, *scl, *shf;
    cudaGetSymbolAddress((void**)&Wpre, g_Wpre);
    cudaGetSymbolAddress((void**)&lnp,  g_ln);
    cudaGetSymbolAddress((void**)&scl,  g_scale);
    cudaGetSymbolAddress((void**)&shf,  g_shift);

    setup_kernel<<<4, 256>>>(bz, bh, zg, zb, zm, zv, hg, hbb, hm, hv);   // launch 1

    dim3 gg(MROWS / GBM, DOUT / GBN);
    gemm_nt2<0><<<gg, 256>>>(x, Wz, Wh, 512, Wpre, MROWS, DOUT, NF, scl, shf);  // launch 2

    dummy_kernel<<<1, 32>>>();   // launch 3 — puts ligru in the ncu capture slot (#4)

    ligru_kernel<<<128, 256>>>(U);                                       // launch 4

    ln_kernel<<<MROWS, 256>>>(lng, lnb);

    gemm_nt2<1><<<gg, 256>>>(lnp, pjW, pjW, DOUT, out, MROWS, DOUT, DOUT, pjb, pjb);

    int tail = out_size - MROWS * DOUT;
    if (tail > 0) tail_kernel<<<1, 32>>>(xlen, out, tail > NB ? NB : tail);
}

// round 14
// speedup vs baseline: 1.8179x; 1.1968x over previous
#include <cuda_runtime.h>
#include <math.h>
#include <stdint.h>

#define NB   16
#define NT   1000
#define NF   512
#define NH   512
#define NSEQ 2000
#define MROWS (NB*NT)   /* 16000 */
#define DOUT  1024      /* 2H */

#define GBM 128
#define GBN 128
#define GBK 16

typedef unsigned long long ull;

// ---------------- f32x2 packed helpers (sm_100+) ----------------
__device__ __forceinline__ ull f2pk(float lo, float hi) {
    ull r; asm("mov.b64 %0, {%1, %2};" : "=l"(r) : "f"(lo), "f"(hi)); return r;
}
__device__ __forceinline__ float2 f2unpk(ull v) {
    float2 r; asm("mov.b64 {%0, %1}, %2;" : "=f"(r.x), "=f"(r.y) : "l"(v)); return r;
}
__device__ __forceinline__ void fma2(ull& d, ull a, ull b) {
    asm("fma.rn.f32x2 %0, %1, %2, %0;" : "+l"(d) : "l"(a), "l"(b));
}

// ---------------- scratch (device globals; no runtime allocation) ----------------
__device__ float g_Wpre[MROWS*DOUT];        // [b][t][n]  BN(x@[Wz;Wh]^T+b)
__device__ float g_H[NSEQ*NB*NH];           // [s][b][j]  all hidden states
__device__ float g_ln[MROWS*DOUT];          // layernorm output
__device__ float g_hbuf[8][2][2*NH];        // [group][parity][b*512+j]
__device__ int   g_arrv[8];                 // per-group arrival counters
__device__ float g_scale[DOUT];             // folded BN scale
__device__ float g_shift[DOUT];             // folded BN shift (incl. gemm bias)

// ---------------- setup: fold BN + bias, reset counters ----------------
__global__ void setup_kernel(const float* __restrict__ bz, const float* __restrict__ bh,
                             const float* __restrict__ zg, const float* __restrict__ zb,
                             const float* __restrict__ zm, const float* __restrict__ zv,
                             const float* __restrict__ hg, const float* __restrict__ hb,
                             const float* __restrict__ hm, const float* __restrict__ hv)
{
    int n = blockIdx.x * blockDim.x + threadIdx.x;
    if (n < 512) {
        float sc = zg[n] * rsqrtf(zv[n] + 1e-5f);
        g_scale[n] = sc;
        g_shift[n] = (bz[n] - zm[n]) * sc + zb[n];
    } else if (n < 1024) {
        int m = n - 512;
        float sc = hg[m] * rsqrtf(hv[m] + 1e-5f);
        g_scale[n] = sc;
        g_shift[n] = (bh[m] - hm[m]) * sc + hb[m];
    }
    if (blockIdx.x == 0 && threadIdx.x < 8) g_arrv[threadIdx.x] = 0;
}

__global__ void dummy_kernel() {}   // ncu capture-slot alignment (slot lands on ligru)

// ---------------- 128x128x16 f32x2 GEMM, crossbar-balanced (unchanged from R13) ----------------
template<int MODE>
__global__ __launch_bounds__(256, 2)
void gemm_nt2(const float* __restrict__ A,
              const float* __restrict__ B0, const float* __restrict__ B1, int nsplit,
              float* __restrict__ C, int M, int N, int K,
              const float* __restrict__ e0, const float* __restrict__ e1)
{
    __shared__ float As[2][GBK][GBM + 4];
    __shared__ float Bs[2][GBK][GBN + 4];

    const int m0 = blockIdx.x * GBM;
    const int n0 = blockIdx.y * GBN;
    const int tid = threadIdx.x;

    const int lr  = tid >> 1;
    const int lks = (tid & 1) * 8;

    const int tx = tid & 15;
    const int ty = tid >> 4;

    const int nrow = n0 + lr;
    const float* brow = (nrow < nsplit) ? (B0 + (size_t)nrow * K)
                                        : (B1 + (size_t)(nrow - nsplit) * K);
    const float* arow = A + (size_t)(m0 + lr) * K;

    ull acc[2][4][2][2];
#pragma unroll
    for (int a = 0; a < 2; a++)
#pragma unroll
        for (int i = 0; i < 4; i++)
#pragma unroll
            for (int b = 0; b < 2; b++) { acc[a][i][b][0] = 0ull; acc[a][i][b][1] = 0ull; }

    const int nt = K / GBK;
    float4 ga0, ga1, gb0, gb1;

    ga0 = *(const float4*)(arow + lks);     ga1 = *(const float4*)(arow + lks + 4);
    gb0 = *(const float4*)(brow + lks);     gb1 = *(const float4*)(brow + lks + 4);
#pragma unroll
    for (int i = 0; i < 4; i++) {
        As[0][lks + i][lr]     = ((const float*)&ga0)[i];
        As[0][lks + 4 + i][lr] = ((const float*)&ga1)[i];
        Bs[0][lks + i][lr]     = ((const float*)&gb0)[i];
        Bs[0][lks + 4 + i][lr] = ((const float*)&gb1)[i];
    }
    __syncthreads();

    for (int t = 0; t < nt; t++) {
        const int cur = t & 1;
        if (t + 1 < nt) {
            const int k0 = (t + 1) * GBK;
            ga0 = *(const float4*)(arow + k0 + lks); ga1 = *(const float4*)(arow + k0 + lks + 4);
            gb0 = *(const float4*)(brow + k0 + lks); gb1 = *(const float4*)(brow + k0 + lks + 4);
        }

#pragma unroll
        for (int k = 0; k < GBK; k++) {
            const float* arp = &As[cur][k][0];
            const float* brp = &Bs[cur][k][0];
            float4 a0 = *(const float4*)(arp + ty * 4);
            float4 a1 = *(const float4*)(arp + 64 + ty * 4);
            ulonglong2 b01 = *(const ulonglong2*)(brp + tx * 4);
            ulonglong2 b23 = *(const ulonglong2*)(brp + 64 + tx * 4);

            ull ap[2][4];
            ap[0][0] = f2pk(a0.x, a0.x); ap[0][1] = f2pk(a0.y, a0.y);
            ap[0][2] = f2pk(a0.z, a0.z); ap[0][3] = f2pk(a0.w, a0.w);
            ap[1][0] = f2pk(a1.x, a1.x); ap[1][1] = f2pk(a1.y, a1.y);
            ap[1][2] = f2pk(a1.z, a1.z); ap[1][3] = f2pk(a1.w, a1.w);

#pragma unroll
            for (int mb = 0; mb < 2; mb++)
#pragma unroll
                for (int i = 0; i < 4; i++) {
                    fma2(acc[mb][i][0][0], ap[mb][i], b01.x);
                    fma2(acc[mb][i][0][1], ap[mb][i], b01.y);
                    fma2(acc[mb][i][1][0], ap[mb][i], b23.x);
                    fma2(acc[mb][i][1][1], ap[mb][i], b23.y);
                }
        }

        if (t + 1 < nt) {
            const int nxt = (t + 1) & 1;
#pragma unroll
            for (int i = 0; i < 4; i++) {
                As[nxt][lks + i][lr]     = ((const float*)&ga0)[i];
                As[nxt][lks + 4 + i][lr] = ((const float*)&ga1)[i];
                Bs[nxt][lks + i][lr]     = ((const float*)&gb0)[i];
                Bs[nxt][lks + 4 + i][lr] = ((const float*)&gb1)[i];
            }
            __syncthreads();
        }
    }

#pragma unroll
    for (int mb = 0; mb < 2; mb++)
#pragma unroll
        for (int i = 0; i < 4; i++) {
            const int m = m0 + mb * 64 + ty * 4 + i;
#pragma unroll
            for (int nb = 0; nb < 2; nb++) {
                const int n = n0 + nb * 64 + tx * 4;
                float2 p0 = f2unpk(acc[mb][i][nb][0]);
                float2 p1 = f2unpk(acc[mb][i][nb][1]);
                float4 v = make_float4(p0.x, p0.y, p1.x, p1.y);
                if (MODE == 0) {
                    float4 s = *(const float4*)&e0[n];
                    float4 h = *(const float4*)&e1[n];
                    v.x = v.x * s.x + h.x; v.y = v.y * s.y + h.y;
                    v.z = v.z * s.z + h.z; v.w = v.w * s.w + h.w;
                } else {
                    float4 bb = *(const float4*)&e0[n];
                    v.x = tanhf(v.x + bb.x); v.y = tanhf(v.y + bb.y);
                    v.z = tanhf(v.z + bb.z); v.w = tanhf(v.w + bb.w);
                }
                *(float4*)&C[(size_t)m * N + n] = v;
            }
        }
}

// ---------------- persistent LiGRU recurrence (R3 reduce, gpu-scope sync) ----------------
// 128 CTAs: 8 groups x 16 CTAs. Group g owns batch rows {2g, 2g+1}.
// CTA c owns j in [32c, 32c+32). warp = k-slice (8 x 64), lane = j.
// U slice in registers as f32x2 pairs; smem-reduce across 8 warps; tid<64 epilogue.
// Sync (ONLY change vs R13): no threadfence; bar -> tid0 red.release.gpu +
// ld.acquire.gpu spin (gpu-scope, ~300-cyc poll quantum instead of sys-scope
// volatile ~2000); bar; one ldcg.128/thread reload.
__global__ __launch_bounds__(256, 1)
void ligru_kernel(const float* __restrict__ U)
{
    const int g   = blockIdx.x >> 4;   // 0..7
    const int c   = blockIdx.x & 15;   // 0..15
    const int tid = threadIdx.x;
    const int w   = tid >> 5;          // 0..7  (k-slice)
    const int l   = tid & 31;          // 0..31 (j within slice)
    const int j   = c * 32 + l;        // 0..511
    const int kb  = w * 64;            // k base

    // U slice in registers, pre-packed as f32x2 pairs (64 floats -> 32 ull per gate)
    ull Uz2[32], Uh2[32];
    {
        const ulonglong2* uz = (const ulonglong2*)(U + (size_t)j * NH + kb);
        const ulonglong2* uh = (const ulonglong2*)(U + (size_t)(512 + j) * NH + kb);
#pragma unroll
        for (int i = 0; i < 16; i++) {
            ulonglong2 a = uz[i]; Uz2[2*i] = a.x; Uz2[2*i+1] = a.y;
            ulonglong2 b = uh[i]; Uh2[2*i] = b.x; Uh2[2*i+1] = b.y;
        }
    }

    __shared__ float hsm[2 * NH];
    __shared__ float red[8][32][5];   // [warp][j][{az0,az1,ah0,ah1}] pad->5
    for (int i = tid; i < 2 * NH; i += 256) hsm[i] = 0.f;
    __syncthreads();

    const int bo = (tid >> 5) & 1;
    const int jo = tid & 31;
    const int jg = c * 32 + jo;
    const int bglob = 2 * g + bo;
    int* arrp = &g_arrv[g];

#pragma unroll 1
    for (int s = 0; s < NSEQ; s++) {
        // prefetch this step's gate pre-activations
        float wzv = 0.f, whv = 0.f;
        if (tid < 64) {
            int srcb, tt;
            if (s < NT) { srcb = bglob;          tt = s; }
            else        { srcb = NB - 1 - bglob; tt = s - NT; }
            const float* wp = g_Wpre + ((size_t)srcb * NT + tt) * DOUT;
            wzv = __ldg(wp + jg);
            whv = __ldg(wp + 512 + jg);
        }

        // partial dots over this warp's k-slice, both batches, both gates (f32x2)
        ull az0 = 0ull, az1 = 0ull, ah0 = 0ull, ah1 = 0ull;
        {
            const ulonglong2* h0 = (const ulonglong2*)&hsm[0] + (kb >> 2);
            const ulonglong2* h1 = (const ulonglong2*)&hsm[NH] + (kb >> 2);
#pragma unroll
            for (int q = 0; q < 16; q++) {
                ulonglong2 v0 = h0[q];
                fma2(az0, Uz2[2*q], v0.x); fma2(az0, Uz2[2*q+1], v0.y);
                fma2(ah0, Uh2[2*q], v0.x); fma2(ah0, Uh2[2*q+1], v0.y);
                ulonglong2 v1 = h1[q];
                fma2(az1, Uz2[2*q], v1.x); fma2(az1, Uz2[2*q+1], v1.y);
                fma2(ah1, Uh2[2*q], v1.x); fma2(ah1, Uh2[2*q+1], v1.y);
            }
        }
        {
            float2 p;
            p = f2unpk(az0); red[w][l][0] = p.x + p.y;
            p = f2unpk(az1); red[w][l][1] = p.x + p.y;
            p = f2unpk(ah0); red[w][l][2] = p.x + p.y;
            p = f2unpk(ah1); red[w][l][3] = p.x + p.y;
        }
        __syncthreads();

        if (tid < 64) {
            float uz = 0.f, uh = 0.f;
#pragma unroll
            for (int ww = 0; ww < 8; ww++) {
                uz += red[ww][jo][bo];
                uh += red[ww][jo][2 + bo];
            }
            float zt = 1.f / (1.f + expf(-(wzv + uz)));
            float hc = fmaxf(whv + uh, 0.f);
            float ho = hsm[bo * NH + jg];
            float hn = zt * ho + (1.f - zt) * hc;
            g_hbuf[g][(s + 1) & 1][bo * NH + jg] = hn;
            g_H[((size_t)s * NB + bglob) * NH + jg] = hn;
            // NO __threadfence: visibility provided by bar + red.release cumulativity
        }
        __syncthreads();   // all leaders' stores ordered before tid0's release

        // group barrier: gpu-scope release arrive + gpu-scope acquire spin
        if (tid == 0) {
            asm volatile("red.release.gpu.global.add.s32 [%0], 1;"
                         :: "l"(arrp) : "memory");
            const int target = 16 * (s + 1);
            int v;
            do {
                asm volatile("ld.acquire.gpu.global.s32 %0, [%1];"
                             : "=r"(v) : "l"(arrp) : "memory");
            } while (v < target);
        }
        __syncthreads();   // tid0's acquire ordered before everyone's reload

        // reload full group h: one ldcg.128 per thread
        {
            const float4* src = (const float4*)&g_hbuf[g][(s + 1) & 1][0];
            float4 hv = __ldcg(src + tid);
            *(float4*)&hsm[tid * 4] = hv;
        }
        __syncthreads();
    }
}

// ---------------- LayerNorm over gathered bidirectional output ----------------
__global__ __launch_bounds__(256)
void ln_kernel(const float* __restrict__ lng, const float* __restrict__ lnb)
{
    const int r = blockIdx.x;            // 0..15999 = b*1000 + t
    const int b = r / NT, t = r - b * NT;
    const int tid = threadIdx.x;

    const float* s0 = g_H + ((size_t)t * NB + b) * NH;                   // forward
    const float* s1 = g_H + ((size_t)(NT + t) * NB + (NB - 1 - b)) * NH; // backward

    float v0 = s0[tid], v1 = s0[tid + 256];
    float v2 = s1[tid], v3 = s1[tid + 256];

    float s  = v0 + v1 + v2 + v3;
    float sq = v0*v0 + v1*v1 + v2*v2 + v3*v3;

    for (int o = 16; o; o >>= 1) {
        s  += __shfl_down_sync(0xffffffffu, s,  o);
        sq += __shfl_down_sync(0xffffffffu, sq, o);
    }
    __shared__ float rs_[8], rq_[8];
    __shared__ float mu_s, rstd_s;
    if ((tid & 31) == 0) { rs_[tid >> 5] = s; rq_[tid >> 5] = sq; }
    __syncthreads();
    if (tid == 0) {
        float S = 0.f, Q = 0.f;
#pragma unroll
        for (int i = 0; i < 8; i++) { S += rs_[i]; Q += rq_[i]; }
        float mu = S * (1.f / 1024.f);
        float var = Q * (1.f / 1024.f) - mu * mu;
        mu_s = mu;
        rstd_s = rsqrtf(var + 1e-5f);
    }
    __syncthreads();
    const float mu = mu_s, rs = rstd_s;

    float* o = g_ln + (size_t)r * DOUT;
    o[tid]        = (v0 - mu) * rs * lng[tid]        + lnb[tid];
    o[tid + 256]  = (v1 - mu) * rs * lng[tid + 256]  + lnb[tid + 256];
    o[tid + 512]  = (v2 - mu) * rs * lng[tid + 512]  + lnb[tid + 512];
    o[tid + 768]  = (v3 - mu) * rs * lng[tid + 768]  + lnb[tid + 768];
}

// ---------------- x_len passthrough tail ----------------
__global__ void tail_kernel(const int* __restrict__ xl, float* __restrict__ out, int n)
{
    int i = threadIdx.x;
    if (i < n) out[(size_t)MROWS * DOUT + i] = (float)xl[i];
}

// ---------------- launch ----------------
extern "C" void kernel_launch(void* const* d_in, const int* in_sizes, int n_in,
                              void* d_out, int out_size)
{
    const float* x    = (const float*)d_in[0];
    const int*   xlen = (const int*)  d_in[1];
    const float* Wz   = (const float*)d_in[2];
    const float* bz   = (const float*)d_in[3];
    const float* Wh   = (const float*)d_in[4];
    const float* bh   = (const float*)d_in[5];
    const float* U    = (const float*)d_in[6];
    const float* zg   = (const float*)d_in[7];
    const float* zb   = (const float*)d_in[8];
    const float* zm   = (const float*)d_in[9];
    const float* zv   = (const float*)d_in[10];
    const float* hg   = (const float*)d_in[11];
    const float* hbb  = (const float*)d_in[12];
    const float* hm   = (const float*)d_in[13];
    const float* hv   = (const float*)d_in[14];
    const float* lng  = (const float*)d_in[15];
    const float* lnb  = (const float*)d_in[16];
    const float* pjW  = (const float*)d_in[17];
    const float* pjb  = (const float*)d_in[18];
    float* out = (float*)d_out;

    float *Wpre, *lnp, *scl, *shf;
    cudaGetSymbolAddress((void**)&Wpre, g_Wpre);
    cudaGetSymbolAddress((void**)&lnp,  g_ln);
    cudaGetSymbolAddress((void**)&scl,  g_scale);
    cudaGetSymbolAddress((void**)&shf,  g_shift);

    setup_kernel<<<4, 256>>>(bz, bh, zg, zb, zm, zv, hg, hbb, hm, hv);   // launch 1

    dim3 gg(MROWS / GBM, DOUT / GBN);
    gemm_nt2<0><<<gg, 256>>>(x, Wz, Wh, 512, Wpre, MROWS, DOUT, NF, scl, shf);  // launch 2

    dummy_kernel<<<1, 32>>>();   // launch 3 — ligru lands in the ncu capture slot

    ligru_kernel<<<128, 256>>>(U);                                       // launch 4

    ln_kernel<<<MROWS, 256>>>(lng, lnb);

    gemm_nt2<1><<<gg, 256>>>(lnp, pjW, pjW, DOUT, out, MROWS, DOUT, DOUT, pjb, pjb);

    int tail = out_size - MROWS * DOUT;
    if (tail > 0) tail_kernel<<<1, 32>>>(xlen, out, tail > NB ? NB : tail);
}